// round 15
// baseline (speedup 1.0000x reference)
#include <cuda_runtime.h>
#include <cstdint>
#include <math.h>

// ============================================================================
// YOLOv3 post-processor: sigmoid -> top-4096 -> decode/clip -> greedy NMS(300)
// -> [16, 300, 6] (box4 | score | label)
// 3 kernels: front(hist+barrier+compact+decode), mega(radix sort + PIPELINED
// NMS), labels. Kept-candidate slots are globally p-ASCENDING so the stable
// radix sort reproduces the reference (score desc, p asc) order exactly.
// ============================================================================

namespace yolo {

constexpr int NBATCH = 16, A = 3, H = 160, W = 160, C = 80;
constexpr int P = A * H * W;       // 76800
constexpr int HW = H * W;          // 25600
constexpr int TOPK = 4096;
constexpr int KEEP = 300;
constexpr int NBINS = 2048;        // top 11 bits of logit order-key
constexpr int SHIFT = 21;          // 32 - 11
constexpr int NGRP = 64;           // bin groups of 32
constexpr int NCHUNK = 16;
constexpr int CH = P / NCHUNK;     // 4800 elements (1600 rems x 3 anchors)
constexpr int REMC = HW / NCHUNK;  // 1600
constexpr int NWARP = 16;          // warps per front block (512 threads)
constexpr int WPC = CH / NWARP;    // 300 elements per warp
constexpr int WIT = (WPC + 31) / 32;  // 10 iterations per warp
constexpr int NBLK = NBATCH * NCHUNK;   // 256 front blocks
constexpr int NMSC = TOPK / 128;   // 32 NMS chunks of 128
constexpr float XCLIP = 4.135166556742356f;   // log(1000/16)
constexpr float IMGMX = 639.0f;               // 640 - TO_REMOVE

typedef unsigned long long u64;

// ---- scratch ----
__device__ uint32_t d_histB[NBATCH * NCHUNK * NBINS];
__device__ uint32_t d_histG[NBATCH * NCHUNK * NGRP];
__device__ u64      d_ckeys[NBATCH * TOPK];
__device__ float4   d_cbox[NBATCH * TOPK];
__device__ int      d_keptP[NBATCH * KEEP];
__device__ int      d_keptN[NBATCH];
__device__ unsigned d_bar;          // monotone ticket counter (never reset)

// order-preserving uint key of a float
__device__ __forceinline__ uint32_t lkey(float v) {
    uint32_t u = __float_as_uint(v);
    return u ^ (uint32_t)(((int)u >> 31) | 0x80000000);
}
// exact sigmoid key (sigmoid >= 0 -> set sign bit); candidates only
__device__ __forceinline__ uint32_t skey(float logit) {
    float s = 1.0f / (1.0f + expf(-logit));
    return __float_as_uint(s) | 0x80000000u;
}

// ----------------------------------------------------------------------------
// front: hist -> device-wide spin barrier -> threshold -> compact + decode.
__global__ __launch_bounds__(512) void k_front(const float* __restrict__ obj,
                                               const float* __restrict__ anchors,
                                               const float* __restrict__ reg) {
    __shared__ float    sdata[CH];       // 19.2 KB: [a*REMC + rloc]
    __shared__ uint32_t sh[NBINS];       // 8 KB
    __shared__ uint32_t gsum[NGRP];
    __shared__ uint32_t binTot[32];
    __shared__ uint32_t hiCnt[NCHUNK], tCnt[NCHUNK];
    __shared__ int sSeg, sT;
    __shared__ uint32_t sAccHi;
    __shared__ unsigned sChunkBase;
    __shared__ int sCq;
    __shared__ unsigned whi[NWARP], wtq[NWARP], whiB[NWARP], wtqB[NWARP];

    const int n = blockIdx.y, bx = blockIdx.x;
    const int t = threadIdx.x;
    const int lane = t & 31, warp = t >> 5;
    const int remBase = bx * REMC;

    // --- phase A: load 3 plane segments (coalesced) + histogram ---
    for (int i = t; i < NBINS; i += 512) sh[i] = 0;
    __syncthreads();
    #pragma unroll
    for (int a = 0; a < A; a++) {
        const float4* p4 = (const float4*)(obj + (size_t)n * P + (size_t)a * HW + remBase);
        float4* s4 = (float4*)(sdata + a * REMC);
        for (int r = t; r < REMC / 4; r += 512) {
            float4 v = p4[r];
            s4[r] = v;
            atomicAdd(&sh[lkey(v.x) >> SHIFT], 1u);
            atomicAdd(&sh[lkey(v.y) >> SHIFT], 1u);
            atomicAdd(&sh[lkey(v.z) >> SHIFT], 1u);
            atomicAdd(&sh[lkey(v.w) >> SHIFT], 1u);
        }
    }
    __syncthreads();
    uint32_t* hb0 = d_histB + (size_t)(n * NCHUNK + bx) * NBINS;
    for (int i = t; i < NBINS; i += 512) hb0[i] = sh[i];
    if (t < NGRP) {
        uint32_t s = 0;
        #pragma unroll
        for (int b = 0; b < 32; b++) s += sh[t * 32 + b];
        d_histG[(size_t)(n * NCHUNK + bx) * NGRP + t] = s;
    }

    // --- device-wide barrier (256 blocks all resident) ---
    __threadfence();
    __syncthreads();
    if (t == 0) {
        unsigned ticket = atomicAdd(&d_bar, 1u);
        unsigned target = (ticket & ~(unsigned)(NBLK - 1)) + NBLK;
        volatile unsigned* vb = &d_bar;
        while (*vb < target) __nanosleep(128);
        __threadfence();
    }
    __syncthreads();

    // --- phase B: threshold (coarse via d_histG, fine via d_histB) ---
    const uint32_t* hb = d_histB + (size_t)n * NCHUNK * NBINS;
    const uint32_t* hg = d_histG + (size_t)n * NCHUNK * NGRP;
    if (t < NGRP) {
        uint32_t s = 0;
        #pragma unroll
        for (int c = 0; c < NCHUNK; c++) s += hg[(size_t)c * NGRP + t];
        gsum[t] = s;
    }
    __syncthreads();
    if (t == 0) {
        uint32_t acc = 0;
        int seg = 0;
        for (int g = NGRP - 1; g >= 0; g--) {
            if (acc + gsum[g] >= (uint32_t)TOPK) { seg = g; break; }
            acc += gsum[g];
        }
        sSeg = seg;
        sAccHi = acc;
    }
    __syncthreads();
    int seg = sSeg;
    if (t < 32) {
        uint32_t s = 0;
        #pragma unroll
        for (int c = 0; c < NCHUNK; c++) s += hb[(size_t)c * NBINS + seg * 32 + t];
        binTot[t] = s;
    }
    __syncthreads();
    if (t == 0) {
        uint32_t acc = sAccHi;
        int T = seg * 32;
        for (int b = 31; b >= 0; b--) {
            acc += binTot[b];
            if (acc >= (uint32_t)TOPK) { T = seg * 32 + b; break; }
        }
        sT = T;
    }
    __syncthreads();
    int T = sT;
    if (warp < NCHUNK) {
        uint32_t s = 0;
        for (int g = seg + 1 + lane; g < NGRP; g += 32)
            s += hg[(size_t)warp * NGRP + g];
        int b = seg * 32 + lane;
        if (b > T) s += hb[(size_t)warp * NBINS + b];
        s = __reduce_add_sync(0xFFFFFFFFu, s);
        if (lane == 0) {
            hiCnt[warp] = s;
            tCnt[warp] = hb[(size_t)warp * NBINS + T];
        }
    }
    __syncthreads();
    if (t == 0) {
        unsigned totalHi = 0;
        #pragma unroll
        for (int c = 0; c < NCHUNK; c++) totalHi += hiCnt[c];
        int quota = TOPK - (int)totalHi;
        unsigned base = 0;
        int myCq = 0;
        int tqAll = 0;
        #pragma unroll
        for (int c = 0; c < NCHUNK; c++) {
            int cq = quota - tqAll;
            if (cq < 0) cq = 0;
            if (cq > (int)tCnt[c]) cq = (int)tCnt[c];
            if (c == bx) { sChunkBase = base; myCq = cq; }
            base += hiCnt[c] + (unsigned)cq;
            tqAll += (int)tCnt[c];
        }
        sCq = myCq;
    }
    __syncthreads();

    // --- pass 1: per-warp hi/tq counts over warp-contiguous p ranges ---
    int chi = 0, ctq = 0;
    #pragma unroll
    for (int it = 0; it < WIT; it++) {
        int off = it * 32 + lane;
        if (off < WPC) {
            int i = warp * WPC + off;
            int a = i % 3, rloc = i / 3;
            int b = (int)(lkey(sdata[a * REMC + rloc]) >> SHIFT);
            chi += (b > T);
            ctq += (b == T);
        }
    }
    unsigned shiW = __reduce_add_sync(0xFFFFFFFFu, (unsigned)chi);
    unsigned stqW = __reduce_add_sync(0xFFFFFFFFu, (unsigned)ctq);
    if (lane == 0) { whi[warp] = shiW; wtq[warp] = stqW; }
    __syncthreads();
    if (t == 0) {
        unsigned h = 0, q = 0;
        #pragma unroll
        for (int w = 0; w < NWARP; w++) {
            whiB[w] = h; h += whi[w];
            wtqB[w] = q; q += wtq[w];
        }
    }
    __syncthreads();

    // --- pass 2: interleaved p-ascending placement + decode ---
    const unsigned chunkBase = sChunkBase;
    const int cq = sCq;
    unsigned hiRun = whiB[warp], tqRun = wtqB[warp];
    u64*    ckeys = d_ckeys + (size_t)n * TOPK;
    float4* cbox  = d_cbox  + (size_t)n * TOPK;
    #pragma unroll 1
    for (int it = 0; it < WIT; it++) {
        int off = it * 32 + lane;
        bool act = off < WPC;
        bool hi = false, tq = false;
        float v = 0.0f;
        int a = 0, rloc = 0;
        if (act) {
            int i = warp * WPC + off;
            a = i % 3; rloc = i / 3;
            v = sdata[a * REMC + rloc];
            int b = (int)(lkey(v) >> SHIFT);
            hi = (b > T);
            tq = (b == T);
        }
        unsigned mhi = __ballot_sync(0xFFFFFFFFu, hi);
        unsigned mtq = __ballot_sync(0xFFFFFFFFu, tq);
        unsigned lm = (1u << lane) - 1u;
        unsigned hiBef = hiRun + __popc(mhi & lm);
        unsigned tqBef = tqRun + __popc(mtq & lm);
        unsigned slot = 0;
        bool wr = false;
        if (hi) {
            unsigned tqK = tqBef < (unsigned)cq ? tqBef : (unsigned)cq;
            slot = chunkBase + hiBef + tqK;
            wr = true;
        } else if (tq && tqBef < (unsigned)cq) {
            slot = chunkBase + hiBef + tqBef;
            wr = true;
        }
        hiRun += __popc(mhi);
        tqRun += __popc(mtq);
        if (wr) {
            int rem = remBase + rloc;
            int p = rem * A + a;             // = bx*CH + i
            ckeys[slot] = ((u64)skey(v) << 32) | ((u64)(uint32_t)(P - 1 - p) << 15)
                        | (u64)slot;
            const float4 anc = *(const float4*)(anchors + ((size_t)n * P + p) * 4);
            float aw = anc.z - anc.x + 1.0f, ah = anc.w - anc.y + 1.0f;
            float acx = anc.x + 0.5f * aw,  acy = anc.y + 0.5f * ah;
            size_t rb = (size_t)((n * A + a) * 4) * HW + (size_t)rem;
            float dx = __ldg(reg + rb);
            float dy = __ldg(reg + rb + HW);
            float dw = fminf(__ldg(reg + rb + 2 * (size_t)HW), XCLIP);
            float dh = fminf(__ldg(reg + rb + 3 * (size_t)HW), XCLIP);
            float pcx = dx * aw + acx, pcy = dy * ah + acy;
            float pw = expf(dw) * aw,  ph = expf(dh) * ah;
            float x1 = pcx - 0.5f * pw, y1 = pcy - 0.5f * ph;
            float x2 = pcx + 0.5f * pw - 1.0f, y2 = pcy + 0.5f * ph - 1.0f;
            x1 = fminf(fmaxf(x1, 0.0f), IMGMX);
            y1 = fminf(fmaxf(y1, 0.0f), IMGMX);
            x2 = fminf(fmaxf(x2, 0.0f), IMGMX);
            y2 = fminf(fmaxf(y2, 0.0f), IMGMX);
            cbox[slot] = make_float4(x1, y1, x2, y2);
        }
    }
}

// ----------------------------------------------------------------------------
#define IOU_GT(px1, py1, px2, py2, pa, qx1, qy1, qx2, qy2, qa, res) {          \
    float _iw = fminf(px2, qx2) - fmaxf(px1, qx1) + 1.0f;                      \
    float _ih = fminf(py2, qy2) - fmaxf(py1, qy1) + 1.0f;                      \
    _iw = fmaxf(_iw, 0.0f); _ih = fmaxf(_ih, 0.0f);                            \
    float _in = _iw * _ih;                                                     \
    res = _in > 0.5f * ((pa) + (qa) - _in);                                    \
}

// mega: 4-pass LSD radix sort -> permute boxes -> PIPELINED 128-chunk NMS.
// Stage A overlaps warp0's serial pick-scan (chunk c) with warps 1-31
// pre-testing chunk c+1 vs the stable kept prefix; stage B delta-tests
// chunk c+1 vs the new picks and builds its suppression matrix.
__global__ __launch_bounds__(1024, 1) void k_mega(float* __restrict__ out) {
    extern __shared__ char raw[];
    u64*   s    = (u64*)raw;                 // 4096*8 = 32 KB
    float* sx1  = (float*)(s + TOPK);        // box SoA, 5*16 KB
    float* sy1  = sx1 + TOPK;
    float* sx2  = sy1 + TOPK;
    float* sy2  = sx2 + TOPK;
    float* sar  = sy2 + TOPK;
    float* kx1  = sar + TOPK;                // kept list, 304 each
    float* ky1  = kx1 + 304;
    float* kx2  = ky1 + 304;
    float* ky2  = kx2 + 304;
    float* kar  = ky2 + 304;
    float* ksc  = kar + 304;
    int*   kp   = (int*)(ksc + 304);
    int*   ssup    = kp + 304;               // 128 final sup flags (chunk c)
    int*   ssupPre = ssup + 128;             // 128 pre-sup flags (chunk c+1)
    unsigned* smat = (unsigned*)(ssupPre + 128); // 128 rows * 4 words
    // sort-time aliases (dead until box SoA is written after sorting)
    u64*      s2    = (u64*)sx1;             // 32 KB ping-pong (sx1+sy1)
    unsigned* whist = (unsigned*)sx2;        // 32 warps * 256 bins (sx2+sy2)
    __shared__ unsigned sdtot[256], sdbase[256];
    __shared__ int snkept, sNp;

    const int n = blockIdx.x;
    const int tid = threadIdx.x;
    const int lane = tid & 31, warp = tid >> 5;

    // ---- load keys (slot order = p-ascending kept order) ----
    for (int i = tid; i < TOPK; i += 1024)
        s[i] = d_ckeys[(size_t)n * TOPK + i];
    if (tid == 0) { snkept = 0; sNp = 0; }
    __syncthreads();

    // ---- 4-pass stable LSD radix, ascending on ~skey (= skey descending) ----
    u64* src = s;
    u64* dst = s2;
    #pragma unroll 1
    for (int pass = 0; pass < 4; pass++) {
        for (int j = tid; j < 32 * 256; j += 1024) whist[j] = 0;
        __syncthreads();
        u64 e[4];
        int dg[4];
        unsigned rk[4];
        const int shift = 8 * pass;
        #pragma unroll
        for (int k = 0; k < 4; k++) {
            u64 ev = src[warp * 128 + k * 32 + lane];
            unsigned key = ~(unsigned)(ev >> 32);
            int d = (int)((key >> shift) & 0xFFu);
            unsigned m = __match_any_sync(0xFFFFFFFFu, d);
            unsigned before = whist[warp * 256 + d];
            __syncwarp();
            unsigned lower = m & ((1u << lane) - 1u);
            rk[k] = before + __popc(lower);
            if (lower == 0) whist[warp * 256 + d] = before + __popc(m);
            __syncwarp();
            e[k] = ev;
            dg[k] = d;
        }
        __syncthreads();
        if (tid < 256) {
            unsigned acc = 0;
            #pragma unroll
            for (int w = 0; w < 32; w++) {
                unsigned tmp = whist[w * 256 + tid];
                whist[w * 256 + tid] = acc;
                acc += tmp;
            }
            sdtot[tid] = acc;
        }
        __syncthreads();
        if (warp == 0) {
            unsigned v[8], tot = 0;
            #pragma unroll
            for (int j = 0; j < 8; j++) { v[j] = sdtot[lane * 8 + j]; tot += v[j]; }
            unsigned inc = tot;
            #pragma unroll
            for (int off = 1; off < 32; off <<= 1) {
                unsigned x = __shfl_up_sync(0xFFFFFFFFu, inc, off);
                if (lane >= off) inc += x;
            }
            unsigned run = inc - tot;
            #pragma unroll
            for (int j = 0; j < 8; j++) { sdbase[lane * 8 + j] = run; run += v[j]; }
        }
        __syncthreads();
        #pragma unroll
        for (int k = 0; k < 4; k++) {
            unsigned pos = sdbase[dg[k]] + whist[warp * 256 + dg[k]] + rk[k];
            dst[pos] = e[k];
        }
        __syncthreads();
        u64* tp = src; src = dst; dst = tp;
    }
    // result in s (even number of passes)

    // ---- permute boxes into sorted order (global gather via slot bits) ----
    for (int i = tid; i < TOPK; i += 1024) {
        unsigned slot = (unsigned)s[i] & 0xFFFu;
        float4 b = d_cbox[(size_t)n * TOPK + slot];
        sx1[i] = b.x; sy1[i] = b.y; sx2[i] = b.z; sy2[i] = b.w;
        sar[i] = (b.z - b.x + 1.0f) * (b.w - b.y + 1.0f);
    }
    __syncthreads();

    // ---- prologue: matrix + sup flags for chunk 0 (no kept list yet) ----
    {
        float ox1[4], oy1[4], ox2[4], oy2[4], oa[4];
        #pragma unroll
        for (int h = 0; h < 4; h++) {
            int idx = warp + 32 * h;
            ox1[h] = sx1[idx]; oy1[h] = sy1[idx];
            ox2[h] = sx2[idx]; oy2[h] = sy2[idx]; oa[h] = sar[idx];
        }
        float qx1[4], qy1[4], qx2[4], qy2[4], qa[4];
        #pragma unroll
        for (int g = 0; g < 4; g++) {
            int idx = g * 32 + lane;
            qx1[g] = sx1[idx]; qy1[g] = sy1[idx];
            qx2[g] = sx2[idx]; qy2[g] = sy2[idx]; qa[g] = sar[idx];
        }
        #pragma unroll
        for (int h = 0; h < 4; h++) {
            unsigned rw[4];
            #pragma unroll
            for (int g = 0; g < 4; g++) {
                bool o;
                IOU_GT(ox1[h], oy1[h], ox2[h], oy2[h], oa[h],
                       qx1[g], qy1[g], qx2[g], qy2[g], qa[g], o);
                rw[g] = __ballot_sync(0xFFFFFFFFu, o);
            }
            if (lane == 0) {
                *(uint4*)&smat[(warp + 32 * h) * 4] =
                    make_uint4(rw[0], rw[1], rw[2], rw[3]);
                ssup[warp + 32 * h] = 0;
            }
        }
    }
    __syncthreads();

    // ---- pipelined NMS main loop ----
    int nk = 0;
    #pragma unroll 1
    for (int c = 0; c < NMSC; c++) {
        if (nk >= KEEP) break;

        // ===== stage A =====
        if (warp == 0) {
            // phase2(chunk c): 128-bit alive scan + kept writes
            const int cb = c * 128;
            unsigned aw0 = ~__ballot_sync(0xFFFFFFFFu, ssup[lane] != 0);
            unsigned aw1 = ~__ballot_sync(0xFFFFFFFFu, ssup[lane + 32] != 0);
            unsigned aw2 = ~__ballot_sync(0xFFFFFFFFu, ssup[lane + 64] != 0);
            unsigned aw3 = ~__ballot_sync(0xFFFFFFFFu, ssup[lane + 96] != 0);
            unsigned aw[4] = {aw0, aw1, aw2, aw3};
            unsigned pk[4] = {0, 0, 0, 0};
            int navail = KEEP - nk;
            int np = 0;
            #pragma unroll 1
            for (int g = 0; g < 4; g++) {
                while (aw[g] && np < navail) {
                    int kk = __ffs(aw[g]) - 1;
                    pk[g] |= 1u << kk;
                    np++;
                    const uint4 row = *(const uint4*)&smat[(g * 32 + kk) * 4];
                    aw[0] &= ~row.x; aw[1] &= ~row.y;
                    aw[2] &= ~row.z; aw[3] &= ~row.w;
                }
                if (np >= navail) break;
            }
            int cum1 = __popc(pk[0]);
            int cum2 = cum1 + __popc(pk[1]);
            int cum3 = cum2 + __popc(pk[2]);
            int cum[4] = {0, cum1, cum2, cum3};
            #pragma unroll
            for (int g = 0; g < 4; g++) {
                if ((pk[g] >> lane) & 1u) {
                    int pos = nk + cum[g] + __popc(pk[g] & ((1u << lane) - 1u));
                    int idx = cb + g * 32 + lane;
                    u64 key = s[idx];
                    kx1[pos] = sx1[idx]; ky1[pos] = sy1[idx];
                    kx2[pos] = sx2[idx]; ky2[pos] = sy2[idx];
                    kar[pos] = sar[idx];
                    ksc[pos] = __uint_as_float((uint32_t)(key >> 32) & 0x7FFFFFFFu);
                    kp[pos]  = P - 1 - (int)(((uint32_t)key >> 15) & 0x1FFFFu);
                }
            }
            if (lane == 0) { snkept = nk + np; sNp = np; }
        } else if (c + 1 < NMSC) {
            // P1pre(chunk c+1): warps 1..31 test vs stable kept[0..nk)
            const int cb2 = (c + 1) * 128;
            int bidx[5];
            float bx1[5], by1[5], bx2[5], by2[5], ba[5];
            int nb = 0;
            for (int b = warp - 1; b < 128; b += 31) {
                int idx = cb2 + b;
                bidx[nb] = b;
                bx1[nb] = sx1[idx]; by1[nb] = sy1[idx];
                bx2[nb] = sx2[idx]; by2[nb] = sy2[idx]; ba[nb] = sar[idx];
                nb++;
            }
            bool sup[5] = {false, false, false, false, false};
            for (int tt = lane; tt < nk; tt += 32) {
                float qx1 = kx1[tt], qy1 = ky1[tt];
                float qx2 = kx2[tt], qy2 = ky2[tt], qa = kar[tt];
                #pragma unroll
                for (int j = 0; j < 5; j++) {
                    if (j < nb) {
                        bool o;
                        IOU_GT(bx1[j], by1[j], bx2[j], by2[j], ba[j],
                               qx1, qy1, qx2, qy2, qa, o);
                        sup[j] |= o;
                    }
                }
            }
            #pragma unroll
            for (int j = 0; j < 5; j++) {
                unsigned any = __ballot_sync(0xFFFFFFFFu, j < nb && sup[j]);
                if (lane == 0 && j < nb) ssupPre[bidx[j]] = (any != 0);
            }
        }
        __syncthreads();

        int np = sNp;
        int nkNew = nk + np;
        if (c + 1 >= NMSC) { nk = nkNew; break; }
        if (nkNew >= KEEP) { nk = nkNew; break; }

        // ===== stage B: delta-test chunk c+1 + build its matrix =====
        {
            const int cb2 = (c + 1) * 128;
            float ox1[4], oy1[4], ox2[4], oy2[4], oa[4];
            #pragma unroll
            for (int h = 0; h < 4; h++) {
                int idx = cb2 + warp + 32 * h;
                ox1[h] = sx1[idx]; oy1[h] = sy1[idx];
                ox2[h] = sx2[idx]; oy2[h] = sy2[idx]; oa[h] = sar[idx];
            }
            bool dsup[4] = {false, false, false, false};
            for (int tt = nk + lane; tt < nkNew; tt += 32) {
                float qx1 = kx1[tt], qy1 = ky1[tt];
                float qx2 = kx2[tt], qy2 = ky2[tt], qa = kar[tt];
                #pragma unroll
                for (int h = 0; h < 4; h++) {
                    bool o;
                    IOU_GT(ox1[h], oy1[h], ox2[h], oy2[h], oa[h],
                           qx1, qy1, qx2, qy2, qa, o);
                    dsup[h] |= o;
                }
            }
            unsigned any[4];
            #pragma unroll
            for (int h = 0; h < 4; h++) {
                unsigned dl = __ballot_sync(0xFFFFFFFFu, dsup[h]);
                any[h] = (unsigned)(ssupPre[warp + 32 * h] != 0) | dl;
            }
            if (lane == 0) {
                #pragma unroll
                for (int h = 0; h < 4; h++) ssup[warp + 32 * h] = (any[h] != 0);
            }
            float qx1[4], qy1[4], qx2[4], qy2[4], qa[4];
            #pragma unroll
            for (int g = 0; g < 4; g++) {
                int idx = cb2 + g * 32 + lane;
                qx1[g] = sx1[idx]; qy1[g] = sy1[idx];
                qx2[g] = sx2[idx]; qy2[g] = sy2[idx]; qa[g] = sar[idx];
            }
            #pragma unroll
            for (int h = 0; h < 4; h++) {
                if (any[h] == 0) {
                    unsigned rw[4];
                    #pragma unroll
                    for (int g = 0; g < 4; g++) {
                        bool o;
                        IOU_GT(ox1[h], oy1[h], ox2[h], oy2[h], oa[h],
                               qx1[g], qy1[g], qx2[g], qy2[g], qa[g], o);
                        rw[g] = __ballot_sync(0xFFFFFFFFu, o);
                    }
                    if (lane == 0)
                        *(uint4*)&smat[(warp + 32 * h) * 4] =
                            make_uint4(rw[0], rw[1], rw[2], rw[3]);
                }
            }
        }
        nk = nkNew;
        __syncthreads();
    }
    __syncthreads();

    // ---- output boxes/scores + export kept rows for the labels kernel ----
    int kept = snkept;
    if (kept > KEEP) kept = KEEP;
    for (int k = tid; k < KEEP; k += 1024) {
        float* o = out + (size_t)(n * KEEP + k) * 6;
        if (k < kept) {
            o[0] = kx1[k]; o[1] = ky1[k]; o[2] = kx2[k]; o[3] = ky2[k];
            o[4] = ksc[k];
            o[5] = 0.0f;
            d_keptP[n * KEEP + k] = kp[k];
        } else {
            o[0] = 0.0f; o[1] = 0.0f; o[2] = 0.0f;
            o[3] = 0.0f; o[4] = 0.0f; o[5] = 0.0f;
        }
    }
    if (tid == 0) d_keptN[n] = kept;
}

// labels: one warp per kept row; argmax over 80 classes
__global__ __launch_bounds__(256) void k_labels(const float* __restrict__ cls,
                                                float* __restrict__ out) {
    int gw = (blockIdx.x * blockDim.x + threadIdx.x) >> 5;
    int lane = threadIdx.x & 31;
    if (gw >= NBATCH * KEEP) return;
    int n = gw / KEEP, k = gw - n * KEEP;
    if (k >= d_keptN[n]) return;
    int p = d_keptP[gw];
    int a = p % A;
    int hw = p / A;
    const float* bp = cls + (size_t)((n * A + a) * C) * HW + (size_t)hw;
    float v0 = __ldg(bp + (size_t)lane * HW);
    float v1 = __ldg(bp + (size_t)(lane + 32) * HW);
    float v2 = (lane + 64 < C) ? __ldg(bp + (size_t)(lane + 64) * HW) : -INFINITY;
    float best = v0;
    int bc = lane;
    if (v1 > best) { best = v1; bc = lane + 32; }
    if (v2 > best) { best = v2; bc = lane + 64; }
    #pragma unroll
    for (int off = 16; off; off >>= 1) {
        float ov = __shfl_xor_sync(0xFFFFFFFFu, best, off);
        int   oc = __shfl_xor_sync(0xFFFFFFFFu, bc, off);
        if (ov > best || (ov == best && oc < bc)) { best = ov; bc = oc; }
    }
    if (lane == 0) out[(size_t)gw * 6 + 5] = (float)(bc + 1);
}

}  // namespace yolo

// ============================================================================
extern "C" void kernel_launch(void* const* d_in, const int* in_sizes, int n_in,
                              void* d_out, int out_size) {
    using namespace yolo;
    const float* anchors = (const float*)d_in[0];   // [16, 76800, 4]
    const float* obj     = (const float*)d_in[1];   // [16, 3, 160, 160]
    const float* reg     = (const float*)d_in[2];   // [16, 12, 160, 160]
    const float* cls     = (const float*)d_in[3];   // [16, 240, 160, 160]
    float* out = (float*)d_out;                     // [16, 300, 6]

    const int MEGA_SMEM = TOPK * (int)sizeof(u64)       // 32768
                        + TOPK * 5 * (int)sizeof(float) // 81920
                        + 304 * 7 * 4                   // 8512
                        + 128 * 4 + 128 * 4 + 128 * 16; // 3072  => 126272

    cudaFuncSetAttribute(k_mega, cudaFuncAttributeMaxDynamicSharedMemorySize,
                         MEGA_SMEM);

    k_front<<<dim3(NCHUNK, NBATCH), 512>>>(obj, anchors, reg);
    k_mega<<<NBATCH, 1024, MEGA_SMEM>>>(out);
    k_labels<<<(NBATCH * KEEP * 32 + 255) / 256, 256>>>(cls, out);
}

// round 16
// speedup vs baseline: 1.0088x; 1.0088x over previous
#include <cuda_runtime.h>
#include <cstdint>
#include <math.h>

// ============================================================================
// YOLOv3 post-processor: sigmoid -> top-4096 -> decode/clip -> greedy NMS(300)
// -> [16, 300, 6] (box4 | score | label)
// 3 kernels: front(hist+barrier+compact+decode), mega(radix sort+NMS), labels
// Kept-candidate slots are globally p-ASCENDING so the stable radix sort
// reproduces the reference (score desc, p asc) order exactly.
// ============================================================================

namespace yolo {

constexpr int NBATCH = 16, A = 3, H = 160, W = 160, C = 80;
constexpr int P = A * H * W;       // 76800
constexpr int HW = H * W;          // 25600
constexpr int TOPK = 4096;
constexpr int KEEP = 300;
constexpr int NBINS = 2048;        // top 11 bits of logit order-key
constexpr int SHIFT = 21;          // 32 - 11
constexpr int NGRP = 64;           // bin groups of 32
constexpr int NCHUNK = 16;
constexpr int CH = P / NCHUNK;     // 4800 elements (1600 rems x 3 anchors)
constexpr int REMC = HW / NCHUNK;  // 1600
constexpr int NWARP = 16;          // warps per front block (512 threads)
constexpr int WPC = CH / NWARP;    // 300 elements per warp
constexpr int WIT = (WPC + 31) / 32;  // 10 iterations per warp
constexpr int NBLK = NBATCH * NCHUNK;   // 256 front blocks
constexpr float XCLIP = 4.135166556742356f;   // log(1000/16)
constexpr float IMGMX = 639.0f;               // 640 - TO_REMOVE

typedef unsigned long long u64;

// ---- scratch ----
__device__ uint32_t d_histB[NBATCH * NCHUNK * NBINS];
__device__ uint32_t d_histG[NBATCH * NCHUNK * NGRP];
__device__ u64      d_ckeys[NBATCH * TOPK];
__device__ float4   d_cbox[NBATCH * TOPK];
__device__ int      d_keptP[NBATCH * KEEP];
__device__ int      d_keptN[NBATCH];
__device__ unsigned d_bar;          // monotone ticket counter (never reset)

// order-preserving uint key of a float
__device__ __forceinline__ uint32_t lkey(float v) {
    uint32_t u = __float_as_uint(v);
    return u ^ (uint32_t)(((int)u >> 31) | 0x80000000);
}
// exact sigmoid key (sigmoid >= 0 -> set sign bit); candidates only
__device__ __forceinline__ uint32_t skey(float logit) {
    float s = 1.0f / (1.0f + expf(-logit));
    return __float_as_uint(s) | 0x80000000u;
}

// ----------------------------------------------------------------------------
// front: hist -> device-wide spin barrier -> threshold -> compact + decode.
__global__ __launch_bounds__(512) void k_front(const float* __restrict__ obj,
                                               const float* __restrict__ anchors,
                                               const float* __restrict__ reg) {
    __shared__ float    sdata[CH];       // 19.2 KB: [a*REMC + rloc]
    __shared__ uint32_t sh[NBINS];       // 8 KB
    __shared__ uint32_t gsum[NGRP];
    __shared__ uint32_t binTot[32];
    __shared__ uint32_t hiCnt[NCHUNK], tCnt[NCHUNK];
    __shared__ int sSeg, sT;
    __shared__ uint32_t sAccHi;
    __shared__ unsigned sChunkBase;
    __shared__ int sCq;
    __shared__ unsigned whi[NWARP], wtq[NWARP], whiB[NWARP], wtqB[NWARP];

    const int n = blockIdx.y, bx = blockIdx.x;
    const int t = threadIdx.x;
    const int lane = t & 31, warp = t >> 5;
    const int remBase = bx * REMC;

    for (int i = t; i < NBINS; i += 512) sh[i] = 0;
    __syncthreads();
    #pragma unroll
    for (int a = 0; a < A; a++) {
        const float4* p4 = (const float4*)(obj + (size_t)n * P + (size_t)a * HW + remBase);
        float4* s4 = (float4*)(sdata + a * REMC);
        for (int r = t; r < REMC / 4; r += 512) {
            float4 v = p4[r];
            s4[r] = v;
            atomicAdd(&sh[lkey(v.x) >> SHIFT], 1u);
            atomicAdd(&sh[lkey(v.y) >> SHIFT], 1u);
            atomicAdd(&sh[lkey(v.z) >> SHIFT], 1u);
            atomicAdd(&sh[lkey(v.w) >> SHIFT], 1u);
        }
    }
    __syncthreads();
    uint32_t* hb0 = d_histB + (size_t)(n * NCHUNK + bx) * NBINS;
    for (int i = t; i < NBINS; i += 512) hb0[i] = sh[i];
    if (t < NGRP) {
        uint32_t s = 0;
        #pragma unroll
        for (int b = 0; b < 32; b++) s += sh[t * 32 + b];
        d_histG[(size_t)(n * NCHUNK + bx) * NGRP + t] = s;
    }

    __threadfence();
    __syncthreads();
    if (t == 0) {
        unsigned ticket = atomicAdd(&d_bar, 1u);
        unsigned target = (ticket & ~(unsigned)(NBLK - 1)) + NBLK;
        volatile unsigned* vb = &d_bar;
        while (*vb < target) __nanosleep(128);
        __threadfence();
    }
    __syncthreads();

    const uint32_t* hb = d_histB + (size_t)n * NCHUNK * NBINS;
    const uint32_t* hg = d_histG + (size_t)n * NCHUNK * NGRP;
    if (t < NGRP) {
        uint32_t s = 0;
        #pragma unroll
        for (int c = 0; c < NCHUNK; c++) s += hg[(size_t)c * NGRP + t];
        gsum[t] = s;
    }
    __syncthreads();
    if (t == 0) {
        uint32_t acc = 0;
        int seg = 0;
        for (int g = NGRP - 1; g >= 0; g--) {
            if (acc + gsum[g] >= (uint32_t)TOPK) { seg = g; break; }
            acc += gsum[g];
        }
        sSeg = seg;
        sAccHi = acc;
    }
    __syncthreads();
    int seg = sSeg;
    if (t < 32) {
        uint32_t s = 0;
        #pragma unroll
        for (int c = 0; c < NCHUNK; c++) s += hb[(size_t)c * NBINS + seg * 32 + t];
        binTot[t] = s;
    }
    __syncthreads();
    if (t == 0) {
        uint32_t acc = sAccHi;
        int T = seg * 32;
        for (int b = 31; b >= 0; b--) {
            acc += binTot[b];
            if (acc >= (uint32_t)TOPK) { T = seg * 32 + b; break; }
        }
        sT = T;
    }
    __syncthreads();
    int T = sT;
    if (warp < NCHUNK) {
        uint32_t s = 0;
        for (int g = seg + 1 + lane; g < NGRP; g += 32)
            s += hg[(size_t)warp * NGRP + g];
        int b = seg * 32 + lane;
        if (b > T) s += hb[(size_t)warp * NBINS + b];
        s = __reduce_add_sync(0xFFFFFFFFu, s);
        if (lane == 0) {
            hiCnt[warp] = s;
            tCnt[warp] = hb[(size_t)warp * NBINS + T];
        }
    }
    __syncthreads();
    if (t == 0) {
        unsigned totalHi = 0;
        #pragma unroll
        for (int c = 0; c < NCHUNK; c++) totalHi += hiCnt[c];
        int quota = TOPK - (int)totalHi;
        unsigned base = 0;
        int myCq = 0;
        int tqAll = 0;
        #pragma unroll
        for (int c = 0; c < NCHUNK; c++) {
            int cq = quota - tqAll;
            if (cq < 0) cq = 0;
            if (cq > (int)tCnt[c]) cq = (int)tCnt[c];
            if (c == bx) { sChunkBase = base; myCq = cq; }
            base += hiCnt[c] + (unsigned)cq;
            tqAll += (int)tCnt[c];
        }
        sCq = myCq;
    }
    __syncthreads();

    int chi = 0, ctq = 0;
    #pragma unroll
    for (int it = 0; it < WIT; it++) {
        int off = it * 32 + lane;
        if (off < WPC) {
            int i = warp * WPC + off;
            int a = i % 3, rloc = i / 3;
            int b = (int)(lkey(sdata[a * REMC + rloc]) >> SHIFT);
            chi += (b > T);
            ctq += (b == T);
        }
    }
    unsigned shiW = __reduce_add_sync(0xFFFFFFFFu, (unsigned)chi);
    unsigned stqW = __reduce_add_sync(0xFFFFFFFFu, (unsigned)ctq);
    if (lane == 0) { whi[warp] = shiW; wtq[warp] = stqW; }
    __syncthreads();
    if (t == 0) {
        unsigned h = 0, q = 0;
        #pragma unroll
        for (int w = 0; w < NWARP; w++) {
            whiB[w] = h; h += whi[w];
            wtqB[w] = q; q += wtq[w];
        }
    }
    __syncthreads();

    const unsigned chunkBase = sChunkBase;
    const int cq = sCq;
    unsigned hiRun = whiB[warp], tqRun = wtqB[warp];
    u64*    ckeys = d_ckeys + (size_t)n * TOPK;
    float4* cbox  = d_cbox  + (size_t)n * TOPK;
    #pragma unroll 1
    for (int it = 0; it < WIT; it++) {
        int off = it * 32 + lane;
        bool act = off < WPC;
        bool hi = false, tq = false;
        float v = 0.0f;
        int a = 0, rloc = 0;
        if (act) {
            int i = warp * WPC + off;
            a = i % 3; rloc = i / 3;
            v = sdata[a * REMC + rloc];
            int b = (int)(lkey(v) >> SHIFT);
            hi = (b > T);
            tq = (b == T);
        }
        unsigned mhi = __ballot_sync(0xFFFFFFFFu, hi);
        unsigned mtq = __ballot_sync(0xFFFFFFFFu, tq);
        unsigned lm = (1u << lane) - 1u;
        unsigned hiBef = hiRun + __popc(mhi & lm);
        unsigned tqBef = tqRun + __popc(mtq & lm);
        unsigned slot = 0;
        bool wr = false;
        if (hi) {
            unsigned tqK = tqBef < (unsigned)cq ? tqBef : (unsigned)cq;
            slot = chunkBase + hiBef + tqK;
            wr = true;
        } else if (tq && tqBef < (unsigned)cq) {
            slot = chunkBase + hiBef + tqBef;
            wr = true;
        }
        hiRun += __popc(mhi);
        tqRun += __popc(mtq);
        if (wr) {
            int rem = remBase + rloc;
            int p = rem * A + a;             // = bx*CH + i
            ckeys[slot] = ((u64)skey(v) << 32) | ((u64)(uint32_t)(P - 1 - p) << 15)
                        | (u64)slot;
            const float4 anc = *(const float4*)(anchors + ((size_t)n * P + p) * 4);
            float aw = anc.z - anc.x + 1.0f, ah = anc.w - anc.y + 1.0f;
            float acx = anc.x + 0.5f * aw,  acy = anc.y + 0.5f * ah;
            size_t rb = (size_t)((n * A + a) * 4) * HW + (size_t)rem;
            float dx = __ldg(reg + rb);
            float dy = __ldg(reg + rb + HW);
            float dw = fminf(__ldg(reg + rb + 2 * (size_t)HW), XCLIP);
            float dh = fminf(__ldg(reg + rb + 3 * (size_t)HW), XCLIP);
            float pcx = dx * aw + acx, pcy = dy * ah + acy;
            float pw = expf(dw) * aw,  ph = expf(dh) * ah;
            float x1 = pcx - 0.5f * pw, y1 = pcy - 0.5f * ph;
            float x2 = pcx + 0.5f * pw - 1.0f, y2 = pcy + 0.5f * ph - 1.0f;
            x1 = fminf(fmaxf(x1, 0.0f), IMGMX);
            y1 = fminf(fmaxf(y1, 0.0f), IMGMX);
            x2 = fminf(fmaxf(x2, 0.0f), IMGMX);
            y2 = fminf(fmaxf(y2, 0.0f), IMGMX);
            cbox[slot] = make_float4(x1, y1, x2, y2);
        }
    }
}

// ----------------------------------------------------------------------------
#define IOU_GT4(pb, pa, qb, qa, res) {                                        \
    float _iw = fminf((pb).z, (qb).z) - fmaxf((pb).x, (qb).x) + 1.0f;          \
    float _ih = fminf((pb).w, (qb).w) - fmaxf((pb).y, (qb).y) + 1.0f;          \
    _iw = fmaxf(_iw, 0.0f); _ih = fmaxf(_ih, 0.0f);                            \
    float _in = _iw * _ih;                                                     \
    res = _in > 0.5f * ((pa) + (qa) - _in);                                    \
}

// mega: 4-pass LSD radix sort (stable) -> permute boxes (float4 SoA) ->
// 128-chunk greedy NMS with early-exit kept-sweeps -> output
__global__ __launch_bounds__(1024, 1) void k_mega(float* __restrict__ out) {
    extern __shared__ char raw[];
    u64*    s    = (u64*)raw;                 // 4096*8 = 32 KB
    float4* sbox = (float4*)(s + TOPK);       // 4096*16 = 64 KB (sorted order)
    float*  sar  = (float*)(sbox + TOPK);     // 16 KB
    float4* kbox = (float4*)(sar + TOPK);     // kept list, 304*16
    float*  kar  = (float*)(kbox + 304);
    float*  ksc  = kar + 304;
    int*    kp   = (int*)(ksc + 304);
    int*    ssup = kp + 304;                  // 128
    unsigned* smat = (unsigned*)(ssup + 128); // 128 rows * 4 words
    // sort-time aliases (sbox is dead until written after sorting)
    u64*      s2    = (u64*)sbox;             // 32 KB ping-pong
    unsigned* whist = (unsigned*)(sbox + 2048); // 32 warps * 256 bins = 32 KB
    __shared__ unsigned sdtot[256], sdbase[256];
    __shared__ int snkept;

    const int n = blockIdx.x;
    const int tid = threadIdx.x;
    const int lane = tid & 31, warp = tid >> 5;

    // ---- load keys (slot order = p-ascending kept order) ----
    for (int i = tid; i < TOPK; i += 1024)
        s[i] = d_ckeys[(size_t)n * TOPK + i];
    if (tid == 0) snkept = 0;
    __syncthreads();

    // ---- 4-pass stable LSD radix, ascending on ~skey (= skey descending) ----
    u64* src = s;
    u64* dst = s2;
    #pragma unroll 1
    for (int pass = 0; pass < 4; pass++) {
        for (int j = tid; j < 32 * 256; j += 1024) whist[j] = 0;
        __syncthreads();
        u64 e[4];
        int dg[4];
        unsigned rk[4];
        const int shift = 8 * pass;
        #pragma unroll
        for (int k = 0; k < 4; k++) {
            u64 ev = src[warp * 128 + k * 32 + lane];
            unsigned key = ~(unsigned)(ev >> 32);
            int d = (int)((key >> shift) & 0xFFu);
            unsigned m = __match_any_sync(0xFFFFFFFFu, d);
            unsigned before = whist[warp * 256 + d];
            __syncwarp();
            unsigned lower = m & ((1u << lane) - 1u);
            rk[k] = before + __popc(lower);
            if (lower == 0) whist[warp * 256 + d] = before + __popc(m);
            __syncwarp();
            e[k] = ev;
            dg[k] = d;
        }
        __syncthreads();
        if (tid < 256) {
            unsigned acc = 0;
            #pragma unroll
            for (int w = 0; w < 32; w++) {
                unsigned tmp = whist[w * 256 + tid];
                whist[w * 256 + tid] = acc;
                acc += tmp;
            }
            sdtot[tid] = acc;
        }
        __syncthreads();
        if (warp == 0) {
            unsigned v[8], tot = 0;
            #pragma unroll
            for (int j = 0; j < 8; j++) { v[j] = sdtot[lane * 8 + j]; tot += v[j]; }
            unsigned inc = tot;
            #pragma unroll
            for (int off = 1; off < 32; off <<= 1) {
                unsigned x = __shfl_up_sync(0xFFFFFFFFu, inc, off);
                if (lane >= off) inc += x;
            }
            unsigned run = inc - tot;
            #pragma unroll
            for (int j = 0; j < 8; j++) { sdbase[lane * 8 + j] = run; run += v[j]; }
        }
        __syncthreads();
        #pragma unroll
        for (int k = 0; k < 4; k++) {
            unsigned pos = sdbase[dg[k]] + whist[warp * 256 + dg[k]] + rk[k];
            dst[pos] = e[k];
        }
        __syncthreads();
        u64* tp = src; src = dst; dst = tp;
    }
    // result in s (even number of passes)

    // ---- permute boxes into sorted order (global gather via slot bits) ----
    for (int i = tid; i < TOPK; i += 1024) {
        unsigned slot = (unsigned)s[i] & 0xFFFu;
        float4 b = d_cbox[(size_t)n * TOPK + slot];
        sbox[i] = b;
        sar[i] = (b.z - b.x + 1.0f) * (b.w - b.y + 1.0f);
    }
    __syncthreads();

    // ---- 128-wide chunked greedy NMS with early-exit kept sweeps ----
    const float4 DUMMY = make_float4(-1e9f, -1e9f, -2e9f, -2e9f);
    for (int c = 0; c < TOPK / 128; c++) {
        int nk = snkept;
        if (nk >= KEEP) break;
        const int cb = c * 128;

        // phase 1: warp w owns boxes cb + w + 32h
        {
            float4 ob[4];
            float oa[4];
            #pragma unroll
            for (int h = 0; h < 4; h++) {
                int idx = cb + warp + 32 * h;
                ob[h] = sbox[idx];
                oa[h] = sar[idx];
            }
            bool sup[4] = {false, false, false, false};
            int nIt = (nk + 31) >> 5;
            #pragma unroll 1
            for (int it = 0; it < nIt; it++) {
                int tt = it * 32 + lane;
                float4 q = DUMMY;
                float qa = 0.0f;
                if (tt < nk) { q = kbox[tt]; qa = kar[tt]; }
                #pragma unroll
                for (int h = 0; h < 4; h++) {
                    bool o;
                    IOU_GT4(ob[h], oa[h], q, qa, o);
                    sup[h] |= o;
                }
                if ((it & 3) == 3) {
                    unsigned b0 = __ballot_sync(0xFFFFFFFFu, sup[0]);
                    unsigned b1 = __ballot_sync(0xFFFFFFFFu, sup[1]);
                    unsigned b2 = __ballot_sync(0xFFFFFFFFu, sup[2]);
                    unsigned b3 = __ballot_sync(0xFFFFFFFFu, sup[3]);
                    if (b0 && b1 && b2 && b3) break;
                }
            }
            unsigned any[4];
            #pragma unroll
            for (int h = 0; h < 4; h++) any[h] = __ballot_sync(0xFFFFFFFFu, sup[h]);
            if (lane == 0) {
                #pragma unroll
                for (int h = 0; h < 4; h++) ssup[warp + 32 * h] = (any[h] != 0);
            }
            // intra-chunk matrix rows only for boxes alive after kept test
            float4 qb[4];
            float qa2[4];
            #pragma unroll
            for (int g = 0; g < 4; g++) {
                int idx = cb + g * 32 + lane;
                qb[g] = sbox[idx];
                qa2[g] = sar[idx];
            }
            #pragma unroll
            for (int h = 0; h < 4; h++) {
                if (any[h] == 0) {
                    unsigned rw[4];
                    #pragma unroll
                    for (int g = 0; g < 4; g++) {
                        bool o;
                        IOU_GT4(ob[h], oa[h], qb[g], qa2[g], o);
                        rw[g] = __ballot_sync(0xFFFFFFFFu, o);
                    }
                    if (lane == 0)
                        *(uint4*)&smat[(warp + 32 * h) * 4] =
                            make_uint4(rw[0], rw[1], rw[2], rw[3]);
                }
            }
        }
        __syncthreads();

        // phase 2: warp 0, 128-bit alive scan
        if (warp == 0) {
            unsigned aw0 = ~__ballot_sync(0xFFFFFFFFu, ssup[lane] != 0);
            unsigned aw1 = ~__ballot_sync(0xFFFFFFFFu, ssup[lane + 32] != 0);
            unsigned aw2 = ~__ballot_sync(0xFFFFFFFFu, ssup[lane + 64] != 0);
            unsigned aw3 = ~__ballot_sync(0xFFFFFFFFu, ssup[lane + 96] != 0);
            unsigned aw[4] = {aw0, aw1, aw2, aw3};
            unsigned pk[4] = {0, 0, 0, 0};
            int navail = KEEP - nk;
            int np = 0;
            #pragma unroll 1
            for (int g = 0; g < 4; g++) {
                while (aw[g] && np < navail) {
                    int kk = __ffs(aw[g]) - 1;
                    pk[g] |= 1u << kk;
                    np++;
                    const uint4 row = *(const uint4*)&smat[(g * 32 + kk) * 4];
                    aw[0] &= ~row.x; aw[1] &= ~row.y;
                    aw[2] &= ~row.z; aw[3] &= ~row.w;
                }
                if (np >= navail) break;
            }
            int cum1 = __popc(pk[0]);
            int cum2 = cum1 + __popc(pk[1]);
            int cum3 = cum2 + __popc(pk[2]);
            int cum[4] = {0, cum1, cum2, cum3};
            #pragma unroll
            for (int g = 0; g < 4; g++) {
                if ((pk[g] >> lane) & 1u) {
                    int pos = nk + cum[g] + __popc(pk[g] & ((1u << lane) - 1u));
                    int idx = cb + g * 32 + lane;
                    u64 key = s[idx];
                    kbox[pos] = sbox[idx];
                    kar[pos] = sar[idx];
                    ksc[pos] = __uint_as_float((uint32_t)(key >> 32) & 0x7FFFFFFFu);
                    kp[pos]  = P - 1 - (int)(((uint32_t)key >> 15) & 0x1FFFFu);
                }
            }
            if (lane == 0) snkept = nk + np;
        }
        __syncthreads();
    }

    // ---- output boxes/scores + export kept rows for the labels kernel ----
    int kept = snkept;
    for (int k = tid; k < KEEP; k += 1024) {
        float* o = out + (size_t)(n * KEEP + k) * 6;
        if (k < kept) {
            float4 b = kbox[k];
            o[0] = b.x; o[1] = b.y; o[2] = b.z; o[3] = b.w;
            o[4] = ksc[k];
            o[5] = 0.0f;
            d_keptP[n * KEEP + k] = kp[k];
        } else {
            o[0] = 0.0f; o[1] = 0.0f; o[2] = 0.0f;
            o[3] = 0.0f; o[4] = 0.0f; o[5] = 0.0f;
        }
    }
    if (tid == 0) d_keptN[n] = kept;
}

// labels: one warp per kept row; argmax over 80 classes
__global__ __launch_bounds__(256) void k_labels(const float* __restrict__ cls,
                                                float* __restrict__ out) {
    int gw = (blockIdx.x * blockDim.x + threadIdx.x) >> 5;
    int lane = threadIdx.x & 31;
    if (gw >= NBATCH * KEEP) return;
    int n = gw / KEEP, k = gw - n * KEEP;
    if (k >= d_keptN[n]) return;
    int p = d_keptP[gw];
    int a = p % A;
    int hw = p / A;
    const float* bp = cls + (size_t)((n * A + a) * C) * HW + (size_t)hw;
    float v0 = __ldg(bp + (size_t)lane * HW);
    float v1 = __ldg(bp + (size_t)(lane + 32) * HW);
    float v2 = (lane + 64 < C) ? __ldg(bp + (size_t)(lane + 64) * HW) : -INFINITY;
    float best = v0;
    int bc = lane;
    if (v1 > best) { best = v1; bc = lane + 32; }
    if (v2 > best) { best = v2; bc = lane + 64; }
    #pragma unroll
    for (int off = 16; off; off >>= 1) {
        float ov = __shfl_xor_sync(0xFFFFFFFFu, best, off);
        int   oc = __shfl_xor_sync(0xFFFFFFFFu, bc, off);
        if (ov > best || (ov == best && oc < bc)) { best = ov; bc = oc; }
    }
    if (lane == 0) out[(size_t)gw * 6 + 5] = (float)(bc + 1);
}

}  // namespace yolo

// ============================================================================
extern "C" void kernel_launch(void* const* d_in, const int* in_sizes, int n_in,
                              void* d_out, int out_size) {
    using namespace yolo;
    const float* anchors = (const float*)d_in[0];   // [16, 76800, 4]
    const float* obj     = (const float*)d_in[1];   // [16, 3, 160, 160]
    const float* reg     = (const float*)d_in[2];   // [16, 12, 160, 160]
    const float* cls     = (const float*)d_in[3];   // [16, 240, 160, 160]
    float* out = (float*)d_out;                     // [16, 300, 6]

    const int MEGA_SMEM = TOPK * (int)sizeof(u64)        // 32768
                        + TOPK * (int)sizeof(float4)     // 65536
                        + TOPK * (int)sizeof(float)      // 16384
                        + 304 * 16 + 304 * 4 * 3         // 8512
                        + 128 * 4 + 128 * 16;            // 2560  => 125760

    cudaFuncSetAttribute(k_mega, cudaFuncAttributeMaxDynamicSharedMemorySize,
                         MEGA_SMEM);

    k_front<<<dim3(NCHUNK, NBATCH), 512>>>(obj, anchors, reg);
    k_mega<<<NBATCH, 1024, MEGA_SMEM>>>(out);
    k_labels<<<(NBATCH * KEEP * 32 + 255) / 256, 256>>>(cls, out);
}